// round 2
// baseline (speedup 1.0000x reference)
#include <cuda_runtime.h>
#include <math_constants.h>

#define T_DIM 64
#define B_DIM 32
#define S_DIM 128
#define E_DIM 512
#define Q_DIM 512
#define H_DIM 256

// Scratch (device globals — no allocation allowed)
__device__ float g_src_proj[B_DIM * H_DIM * S_DIM];   // [b][h][s]  (transposed for coalesced fused reads)
__device__ float g_q_proj[T_DIM * B_DIM * H_DIM];     // [t][b][h]

__device__ __forceinline__ float ex2f_(float x) {
    float y; asm("ex2.approx.f32 %0, %1;" : "=f"(y) : "f"(x)); return y;
}
__device__ __forceinline__ float rcpf_(float x) {
    float y; asm("rcp.approx.f32 %0, %1;" : "=f"(y) : "f"(x)); return y;
}

// ---------------------------------------------------------------------------
// Combined projection GEMM.
// blockIdx.x in [0,32): src path, one b per m-tile (BM=128=S), output transposed [b][h][s].
// blockIdx.x in [32,48): query path, m = (t*B+b), output row-major [m][h].
// C[m,h] = sum_k A[m,k] * W[h,k] + bias[h].  K=512 for both paths.
// Tile: BM=128, BN=64, BK=16, 256 threads, 8x4 microtile.
// ---------------------------------------------------------------------------
__global__ __launch_bounds__(256) void proj_gemm(
    const float* __restrict__ src, const float* __restrict__ Wsrc, const float* __restrict__ bsrc,
    const float* __restrict__ qv,  const float* __restrict__ Wq,   const float* __restrict__ bq)
{
    const int bx = blockIdx.x;      // 0..47
    const int n0 = blockIdx.y * 64; // 0..3 -> h tile base

    const bool is_src = (bx < 32);
    const float* __restrict__ A    = is_src ? (src + (size_t)bx * 128 * E_DIM)
                                            : (qv  + (size_t)(bx - 32) * 128 * Q_DIM);
    const float* __restrict__ W    = is_src ? Wsrc : Wq;
    const float* __restrict__ bias = is_src ? bsrc : bq;

    __shared__ float As[16][128];
    __shared__ float Bs[16][64];

    const int tid = threadIdx.x;
    const int tr  = tid >> 4;        // 0..15 -> 8 rows each
    const int tc  = tid & 15;        // 0..15 -> 4 cols each
    const int ar  = tid >> 2;        // 0..63
    const int ac  = (tid & 3) * 4;   // 0,4,8,12

    float acc[8][4];
#pragma unroll
    for (int i = 0; i < 8; i++)
#pragma unroll
        for (int j = 0; j < 4; j++) acc[i][j] = 0.f;

    for (int kt = 0; kt < 512; kt += 16) {
        float4 a0 = *(const float4*)&A[(size_t)ar        * 512 + kt + ac];
        float4 a1 = *(const float4*)&A[(size_t)(ar + 64) * 512 + kt + ac];
        float4 b0 = *(const float4*)&W[(size_t)(n0 + ar) * 512 + kt + ac];

        As[ac + 0][ar] = a0.x; As[ac + 1][ar] = a0.y; As[ac + 2][ar] = a0.z; As[ac + 3][ar] = a0.w;
        As[ac + 0][ar + 64] = a1.x; As[ac + 1][ar + 64] = a1.y; As[ac + 2][ar + 64] = a1.z; As[ac + 3][ar + 64] = a1.w;
        Bs[ac + 0][ar] = b0.x; Bs[ac + 1][ar] = b0.y; Bs[ac + 2][ar] = b0.z; Bs[ac + 3][ar] = b0.w;
        __syncthreads();

#pragma unroll
        for (int k = 0; k < 16; k++) {
            float4 af0 = *(const float4*)&As[k][tr * 8];
            float4 af1 = *(const float4*)&As[k][tr * 8 + 4];
            float4 bf  = *(const float4*)&Bs[k][tc * 4];
            float a8[8] = {af0.x, af0.y, af0.z, af0.w, af1.x, af1.y, af1.z, af1.w};
            float b4[4] = {bf.x, bf.y, bf.z, bf.w};
#pragma unroll
            for (int i = 0; i < 8; i++)
#pragma unroll
                for (int j = 0; j < 4; j++)
                    acc[i][j] = fmaf(a8[i], b4[j], acc[i][j]);
        }
        __syncthreads();
    }

    if (is_src) {
        const int b = bx;
        float* dst = g_src_proj + (size_t)b * H_DIM * S_DIM;
#pragma unroll
        for (int i = 0; i < 8; i++) {
            const int s = tr * 8 + i;
#pragma unroll
            for (int j = 0; j < 4; j++) {
                const int h = n0 + tc * 4 + j;
                dst[h * S_DIM + s] = acc[i][j] + bias[h];
            }
        }
    } else {
        const int m0 = (bx - 32) * 128;
#pragma unroll
        for (int i = 0; i < 8; i++) {
            const int m = m0 + tr * 8 + i;
#pragma unroll
            for (int j = 0; j < 4; j++) {
                const int h = n0 + tc * 4 + j;
                g_q_proj[(size_t)m * H_DIM + h] = acc[i][j] + bias[h];
            }
        }
    }
}

// ---------------------------------------------------------------------------
// Fused: tanh(src_proj + q_proj) . w2 + b2 -> mask -> softmax over s.
// CTA = (t-group of 4, b). 128 threads, one per s.
// tanh(x) = 1 - 2/(exp(2x)+1) via ex2/rcp (err ~1e-6, branch-free).
// logit = (sum w2 + b2) - 2 * sum_h w2[h] * rcp(ex2((sv+qp)*2log2e)+1)
// ---------------------------------------------------------------------------
__global__ __launch_bounds__(128) void fused_attn(
    const float* __restrict__ w2, const float* __restrict__ b2p,
    const int* __restrict__ mask, float* __restrict__ out)
{
    const int b  = blockIdx.y;
    const int tg = blockIdx.x;       // t = tg*4 + tt
    const int s  = threadIdx.x;      // 0..127

    __shared__ float qs[4][H_DIM];
    __shared__ float w2s[H_DIM];
    __shared__ float redm[4][4];
    __shared__ float reds[4][4];

    const float TWO_LOG2E = 2.885390081777926815f;   // 2/ln(2)
    const float LOG2E     = 1.442695040888963407f;

    for (int idx = s; idx < 4 * H_DIM; idx += 128) {
        const int tt = idx >> 8;
        const int h  = idx & (H_DIM - 1);
        const int t  = tg * 4 + tt;
        qs[tt][h] = g_q_proj[((size_t)t * B_DIM + b) * H_DIM + h] * TWO_LOG2E;
    }
    for (int idx = s; idx < H_DIM; idx += 128) w2s[idx] = w2[idx];
    __syncthreads();

    const float* __restrict__ srcb = g_src_proj + (size_t)b * H_DIM * S_DIM + s;

    float acc0 = 0.f, acc1 = 0.f, acc2 = 0.f, acc3 = 0.f, w2sum = 0.f;
#pragma unroll 4
    for (int h = 0; h < H_DIM; h++) {
        const float sv  = srcb[h * S_DIM] * TWO_LOG2E;
        const float w2h = w2s[h];
        w2sum += w2h;
        float y0 = sv + qs[0][h]; float r0 = rcpf_(ex2f_(y0) + 1.f); acc0 = fmaf(w2h, r0, acc0);
        float y1 = sv + qs[1][h]; float r1 = rcpf_(ex2f_(y1) + 1.f); acc1 = fmaf(w2h, r1, acc1);
        float y2 = sv + qs[2][h]; float r2 = rcpf_(ex2f_(y2) + 1.f); acc2 = fmaf(w2h, r2, acc2);
        float y3 = sv + qs[3][h]; float r3 = rcpf_(ex2f_(y3) + 1.f); acc3 = fmaf(w2h, r3, acc3);
    }

    const float base = w2sum + b2p[0];
    float logit[4] = { base - 2.f * acc0, base - 2.f * acc1,
                       base - 2.f * acc2, base - 2.f * acc3 };

    if (mask[b * S_DIM + s] != 0) {
        const float ninf = __int_as_float(0xff800000);
        logit[0] = ninf; logit[1] = ninf; logit[2] = ninf; logit[3] = ninf;
    }

    const int lane = s & 31;
    const int wid  = s >> 5;

#pragma unroll
    for (int tt = 0; tt < 4; tt++) {
        float m = logit[tt];
#pragma unroll
        for (int off = 16; off >= 1; off >>= 1)
            m = fmaxf(m, __shfl_xor_sync(0xffffffffu, m, off));
        if (lane == 0) redm[tt][wid] = m;
    }
    __syncthreads();

    float e[4];
#pragma unroll
    for (int tt = 0; tt < 4; tt++) {
        const float bm = fmaxf(fmaxf(redm[tt][0], redm[tt][1]),
                               fmaxf(redm[tt][2], redm[tt][3]));
        e[tt] = ex2f_((logit[tt] - bm) * LOG2E);
        float sum = e[tt];
#pragma unroll
        for (int off = 16; off >= 1; off >>= 1)
            sum += __shfl_xor_sync(0xffffffffu, sum, off);
        if (lane == 0) reds[tt][wid] = sum;
    }
    __syncthreads();

#pragma unroll
    for (int tt = 0; tt < 4; tt++) {
        const float tot = (reds[tt][0] + reds[tt][1]) + (reds[tt][2] + reds[tt][3]);
        const int t = tg * 4 + tt;
        out[((size_t)t * B_DIM + b) * S_DIM + s] = e[tt] / tot;
    }
}

extern "C" void kernel_launch(void* const* d_in, const int* in_sizes, int n_in,
                              void* d_out, int out_size)
{
    const float* src  = (const float*)d_in[0];
    const int*   mask = (const int*)d_in[1];
    const float* qv   = (const float*)d_in[2];
    const float* Wsrc = (const float*)d_in[3];
    const float* bsrc = (const float*)d_in[4];
    const float* Wq   = (const float*)d_in[5];
    const float* bq   = (const float*)d_in[6];
    const float* w2   = (const float*)d_in[7];
    const float* b2   = (const float*)d_in[8];
    float*       out  = (float*)d_out;

    dim3 g1(48, 4);
    proj_gemm<<<g1, 256>>>(src, Wsrc, bsrc, qv, Wq, bq);

    dim3 g2(T_DIM / 4, B_DIM);
    fused_attn<<<g2, 128>>>(w2, b2, mask, out);
}

// round 3
// speedup vs baseline: 1.3438x; 1.3438x over previous
#include <cuda_runtime.h>
#include <math_constants.h>

#define T_DIM 64
#define B_DIM 32
#define S_DIM 128
#define E_DIM 512
#define Q_DIM 512
#define H_DIM 256

// Scratch (device globals — no allocation allowed)
__device__ float g_src_proj[B_DIM * H_DIM * S_DIM];   // [b][h][s]  (transposed for coalesced fused reads)
__device__ float g_q_proj[T_DIM * B_DIM * H_DIM];     // [t][b][h]

__device__ __forceinline__ float ex2f_(float x) {
    float y; asm("ex2.approx.f32 %0, %1;" : "=f"(y) : "f"(x)); return y;
}
__device__ __forceinline__ float tanhf_(float x) {
    float y; asm("tanh.approx.f32 %0, %1;" : "=f"(y) : "f"(x)); return y;
}

// ---------------------------------------------------------------------------
// Combined projection GEMM (unchanged from R1 — measured at ~its fp32 floor).
// blockIdx.x in [0,32): src path, one b per m-tile, output transposed [b][h][s].
// blockIdx.x in [32,48): query path, m = (t*B+b), output row-major [m][h].
// ---------------------------------------------------------------------------
__global__ __launch_bounds__(256) void proj_gemm(
    const float* __restrict__ src, const float* __restrict__ Wsrc, const float* __restrict__ bsrc,
    const float* __restrict__ qv,  const float* __restrict__ Wq,   const float* __restrict__ bq)
{
    const int bx = blockIdx.x;      // 0..47
    const int n0 = blockIdx.y * 64; // h tile base

    const bool is_src = (bx < 32);
    const float* __restrict__ A    = is_src ? (src + (size_t)bx * 128 * E_DIM)
                                            : (qv  + (size_t)(bx - 32) * 128 * Q_DIM);
    const float* __restrict__ W    = is_src ? Wsrc : Wq;
    const float* __restrict__ bias = is_src ? bsrc : bq;

    __shared__ float As[16][128];
    __shared__ float Bs[16][64];

    const int tid = threadIdx.x;
    const int tr  = tid >> 4;
    const int tc  = tid & 15;
    const int ar  = tid >> 2;
    const int ac  = (tid & 3) * 4;

    float acc[8][4];
#pragma unroll
    for (int i = 0; i < 8; i++)
#pragma unroll
        for (int j = 0; j < 4; j++) acc[i][j] = 0.f;

    for (int kt = 0; kt < 512; kt += 16) {
        float4 a0 = *(const float4*)&A[(size_t)ar        * 512 + kt + ac];
        float4 a1 = *(const float4*)&A[(size_t)(ar + 64) * 512 + kt + ac];
        float4 b0 = *(const float4*)&W[(size_t)(n0 + ar) * 512 + kt + ac];

        As[ac + 0][ar] = a0.x; As[ac + 1][ar] = a0.y; As[ac + 2][ar] = a0.z; As[ac + 3][ar] = a0.w;
        As[ac + 0][ar + 64] = a1.x; As[ac + 1][ar + 64] = a1.y; As[ac + 2][ar + 64] = a1.z; As[ac + 3][ar + 64] = a1.w;
        Bs[ac + 0][ar] = b0.x; Bs[ac + 1][ar] = b0.y; Bs[ac + 2][ar] = b0.z; Bs[ac + 3][ar] = b0.w;
        __syncthreads();

#pragma unroll
        for (int k = 0; k < 16; k++) {
            float4 af0 = *(const float4*)&As[k][tr * 8];
            float4 af1 = *(const float4*)&As[k][tr * 8 + 4];
            float4 bf  = *(const float4*)&Bs[k][tc * 4];
            float a8[8] = {af0.x, af0.y, af0.z, af0.w, af1.x, af1.y, af1.z, af1.w};
            float b4[4] = {bf.x, bf.y, bf.z, bf.w};
#pragma unroll
            for (int i = 0; i < 8; i++)
#pragma unroll
                for (int j = 0; j < 4; j++)
                    acc[i][j] = fmaf(a8[i], b4[j], acc[i][j]);
        }
        __syncthreads();
    }

    if (is_src) {
        const int b = bx;
        float* dst = g_src_proj + (size_t)b * H_DIM * S_DIM;
#pragma unroll
        for (int i = 0; i < 8; i++) {
            const int s = tr * 8 + i;
#pragma unroll
            for (int j = 0; j < 4; j++) {
                const int h = n0 + tc * 4 + j;
                dst[h * S_DIM + s] = acc[i][j] + bias[h];
            }
        }
    } else {
        const int m0 = (bx - 32) * 128;
#pragma unroll
        for (int i = 0; i < 8; i++) {
            const int m = m0 + tr * 8 + i;
#pragma unroll
            for (int j = 0; j < 4; j++) {
                const int h = n0 + tc * 4 + j;
                g_q_proj[(size_t)m * H_DIM + h] = acc[i][j] + bias[h];
            }
        }
    }
}

// ---------------------------------------------------------------------------
// Fused: tanh(src_proj + q_proj) . w2 + b2 -> mask -> softmax over s.
// CTA = (t-group of 4, b), 512 threads: hg = tid>>7 selects an H-quarter,
// s = tid&127. Each thread accumulates 64 h's for 4 t's; cross-hg reduce via
// smem; then group hg finishes softmax for t = tg*4 + hg.
// tanh via MUFU.TANH (tanh.approx.f32).
// ---------------------------------------------------------------------------
__global__ __launch_bounds__(512) void fused_attn(
    const float* __restrict__ w2, const float* __restrict__ b2p,
    const int* __restrict__ mask, float* __restrict__ out)
{
    const int b   = blockIdx.y;
    const int tg  = blockIdx.x;       // t = tg*4 + tt
    const int tid = threadIdx.x;
    const int s   = tid & 127;
    const int hg  = tid >> 7;         // 0..3

    __shared__ float qs[4][H_DIM];        // [tt][h]
    __shared__ float w2s[H_DIM];
    __shared__ float part[4][4][S_DIM];   // [tt][hg][s]
    __shared__ float redm[4][4];          // [tt][warp-in-group]
    __shared__ float reds[4][4];

    const float LOG2E = 1.442695040888963407f;

    for (int idx = tid; idx < 4 * H_DIM; idx += 512) {
        const int tt = idx >> 8;
        const int h  = idx & (H_DIM - 1);
        const int t  = tg * 4 + tt;
        qs[tt][h] = g_q_proj[((size_t)t * B_DIM + b) * H_DIM + h];
    }
    if (tid < H_DIM) w2s[tid] = w2[tid];
    __syncthreads();

    const float* __restrict__ srcb = g_src_proj + (size_t)b * H_DIM * S_DIM + s;
    const int h0 = hg * 64;

    float a0 = 0.f, a1 = 0.f, a2 = 0.f, a3 = 0.f;
#pragma unroll 8
    for (int i = 0; i < 64; i++) {
        const int h = h0 + i;
        const float sv = srcb[h * S_DIM];
        const float w  = w2s[h];
        a0 = fmaf(w, tanhf_(sv + qs[0][h]), a0);
        a1 = fmaf(w, tanhf_(sv + qs[1][h]), a1);
        a2 = fmaf(w, tanhf_(sv + qs[2][h]), a2);
        a3 = fmaf(w, tanhf_(sv + qs[3][h]), a3);
    }
    part[0][hg][s] = a0;
    part[1][hg][s] = a1;
    part[2][hg][s] = a2;
    part[3][hg][s] = a3;
    __syncthreads();

    // Group hg now owns tt = hg.
    float logit = ((part[hg][0][s] + part[hg][1][s]) +
                   (part[hg][2][s] + part[hg][3][s])) + b2p[0];
    if (mask[b * S_DIM + s] != 0)
        logit = __int_as_float(0xff800000);   // -inf

    const int lane = tid & 31;
    const int gw   = (tid >> 5) & 3;          // warp index within group (s/32)

    float m = logit;
#pragma unroll
    for (int off = 16; off >= 1; off >>= 1)
        m = fmaxf(m, __shfl_xor_sync(0xffffffffu, m, off));
    if (lane == 0) redm[hg][gw] = m;
    __syncthreads();

    const float bm = fmaxf(fmaxf(redm[hg][0], redm[hg][1]),
                           fmaxf(redm[hg][2], redm[hg][3]));
    const float e = ex2f_((logit - bm) * LOG2E);
    float sum = e;
#pragma unroll
    for (int off = 16; off >= 1; off >>= 1)
        sum += __shfl_xor_sync(0xffffffffu, sum, off);
    if (lane == 0) reds[hg][gw] = sum;
    __syncthreads();

    const float tot = (reds[hg][0] + reds[hg][1]) + (reds[hg][2] + reds[hg][3]);
    const int t = tg * 4 + hg;
    out[((size_t)t * B_DIM + b) * S_DIM + s] = e / tot;
}

extern "C" void kernel_launch(void* const* d_in, const int* in_sizes, int n_in,
                              void* d_out, int out_size)
{
    const float* src  = (const float*)d_in[0];
    const int*   mask = (const int*)d_in[1];
    const float* qv   = (const float*)d_in[2];
    const float* Wsrc = (const float*)d_in[3];
    const float* bsrc = (const float*)d_in[4];
    const float* Wq   = (const float*)d_in[5];
    const float* bq   = (const float*)d_in[6];
    const float* w2   = (const float*)d_in[7];
    const float* b2   = (const float*)d_in[8];
    float*       out  = (float*)d_out;

    dim3 g1(48, 4);
    proj_gemm<<<g1, 256>>>(src, Wsrc, bsrc, qv, Wq, bq);

    dim3 g2(T_DIM / 4, B_DIM);
    fused_attn<<<g2, 512>>>(w2, b2, mask, out);
}

// round 4
// speedup vs baseline: 1.4864x; 1.1060x over previous
#include <cuda_runtime.h>
#include <math_constants.h>

#define T_DIM 64
#define B_DIM 32
#define S_DIM 128
#define E_DIM 512
#define Q_DIM 512
#define H_DIM 256

// Scratch (device globals — no allocation allowed)
__device__ float g_src_proj[B_DIM * H_DIM * S_DIM];   // [b][h][s]  (transposed for fused reads)
__device__ float g_q_proj[T_DIM * B_DIM * H_DIM];     // [t][b][h]

__device__ __forceinline__ float ex2f_(float x) {
    float y; asm("ex2.approx.f32 %0, %1;" : "=f"(y) : "f"(x)); return y;
}
__device__ __forceinline__ float tanhf_(float x) {
    float y; asm("tanh.approx.f32 %0, %1;" : "=f"(y) : "f"(x)); return y;
}
__device__ __forceinline__ unsigned tf32_(float x) {
    unsigned r; asm("cvt.rna.tf32.f32 %0, %1;" : "=r"(r) : "f"(x)); return r;
}
__device__ __forceinline__ void mma_tf32(float c[4], const unsigned a[4], const unsigned b[2]) {
    asm volatile(
        "mma.sync.aligned.m16n8k8.row.col.f32.tf32.tf32.f32 "
        "{%0,%1,%2,%3}, {%4,%5,%6,%7}, {%8,%9}, {%0,%1,%2,%3};"
        : "+f"(c[0]), "+f"(c[1]), "+f"(c[2]), "+f"(c[3])
        : "r"(a[0]), "r"(a[1]), "r"(a[2]), "r"(a[3]), "r"(b[0]), "r"(b[1]));
}

// ---------------------------------------------------------------------------
// Tensor-core projection GEMM (3xTF32 -> fp32 accuracy).
// C[m,h] = sum_k A[m,k] * W[h,k] + bias[h],  K=512.
// blockIdx.x in [0,32): src path (A row = s within batch bx), out transposed [b][h][s].
// blockIdx.x in [32,48): query path (A row = t*B+b), out row-major [m][h].
// CTA tile 128(m) x 64(n), 8 warps in 4(m) x 2(n), warp tile 32x32.
// Smem K-chunk = 16, hi/lo tf32 split, row stride 20 (conflict-free frags).
// ---------------------------------------------------------------------------
__global__ __launch_bounds__(256) void proj_gemm(
    const float* __restrict__ src, const float* __restrict__ Wsrc, const float* __restrict__ bsrc,
    const float* __restrict__ qv,  const float* __restrict__ Wq,   const float* __restrict__ bq)
{
    const int bx = blockIdx.x;      // 0..47
    const int n0 = blockIdx.y * 64; // h tile base

    const bool is_src = (bx < 32);
    const float* __restrict__ A    = is_src ? (src + (size_t)bx * 128 * E_DIM)
                                            : (qv  + (size_t)(bx - 32) * 128 * Q_DIM);
    const float* __restrict__ W    = is_src ? Wsrc : Wq;
    const float* __restrict__ bias = is_src ? bsrc : bq;

    __shared__ float Ahi[128][20];
    __shared__ float Alo[128][20];
    __shared__ float Bhi[64][20];
    __shared__ float Blo[64][20];

    const int tid  = threadIdx.x;
    const int warp = tid >> 5;
    const int lane = tid & 31;
    const int wm   = (warp & 3) * 32;   // warp m base
    const int wn   = (warp >> 2) * 32;  // warp n base
    const int frow = lane >> 2;         // fragment row group 0..7
    const int fcol = lane & 3;          // fragment col group 0..3

    float acc[2][4][4];
#pragma unroll
    for (int i = 0; i < 2; i++)
#pragma unroll
        for (int j = 0; j < 4; j++)
#pragma unroll
            for (int r = 0; r < 4; r++) acc[i][j][r] = 0.f;

    for (int kt = 0; kt < 512; kt += 16) {
        // --- load + tf32 hi/lo split into smem ---
        // A tile: 128 x 16 = 512 float4; 2 per thread
#pragma unroll
        for (int j = 0; j < 2; j++) {
            const int v = tid * 2 + j;
            const int r = v >> 2;
            const int c = (v & 3) * 4;
            float4 a = *(const float4*)&A[(size_t)r * 512 + kt + c];
            float av[4] = {a.x, a.y, a.z, a.w};
#pragma unroll
            for (int i = 0; i < 4; i++) {
                const unsigned hi = tf32_(av[i]);
                const float hif = __uint_as_float(hi);
                Ahi[r][c + i] = hif;
                Alo[r][c + i] = __uint_as_float(tf32_(av[i] - hif));
            }
        }
        // W tile: 64 x 16 = 256 float4; 1 per thread
        {
            const int r = tid >> 2;
            const int c = (tid & 3) * 4;
            float4 w = *(const float4*)&W[(size_t)(n0 + r) * 512 + kt + c];
            float wv[4] = {w.x, w.y, w.z, w.w};
#pragma unroll
            for (int i = 0; i < 4; i++) {
                const unsigned hi = tf32_(wv[i]);
                const float hif = __uint_as_float(hi);
                Bhi[r][c + i] = hif;
                Blo[r][c + i] = __uint_as_float(tf32_(wv[i] - hif));
            }
        }
        __syncthreads();

        // --- 2 k-steps of mma ---
#pragma unroll
        for (int ks = 0; ks < 2; ks++) {
            const int k0 = ks * 8;

            unsigned ah[2][4], al[2][4];
#pragma unroll
            for (int mf = 0; mf < 2; mf++) {
                const int m = wm + mf * 16;
                ah[mf][0] = __float_as_uint(Ahi[m + frow    ][k0 + fcol    ]);
                ah[mf][1] = __float_as_uint(Ahi[m + frow + 8][k0 + fcol    ]);
                ah[mf][2] = __float_as_uint(Ahi[m + frow    ][k0 + fcol + 4]);
                ah[mf][3] = __float_as_uint(Ahi[m + frow + 8][k0 + fcol + 4]);
                al[mf][0] = __float_as_uint(Alo[m + frow    ][k0 + fcol    ]);
                al[mf][1] = __float_as_uint(Alo[m + frow + 8][k0 + fcol    ]);
                al[mf][2] = __float_as_uint(Alo[m + frow    ][k0 + fcol + 4]);
                al[mf][3] = __float_as_uint(Alo[m + frow + 8][k0 + fcol + 4]);
            }
            unsigned bh[4][2], bl[4][2];
#pragma unroll
            for (int nf = 0; nf < 4; nf++) {
                const int n = wn + nf * 8;
                bh[nf][0] = __float_as_uint(Bhi[n + frow][k0 + fcol    ]);
                bh[nf][1] = __float_as_uint(Bhi[n + frow][k0 + fcol + 4]);
                bl[nf][0] = __float_as_uint(Blo[n + frow][k0 + fcol    ]);
                bl[nf][1] = __float_as_uint(Blo[n + frow][k0 + fcol + 4]);
            }
#pragma unroll
            for (int mf = 0; mf < 2; mf++)
#pragma unroll
                for (int nf = 0; nf < 4; nf++) {
                    mma_tf32(acc[mf][nf], al[mf], bh[nf]);   // lo*hi
                    mma_tf32(acc[mf][nf], ah[mf], bl[nf]);   // hi*lo
                    mma_tf32(acc[mf][nf], ah[mf], bh[nf]);   // hi*hi
                }
        }
        __syncthreads();
    }

    // --- epilogue ---
    const int crow = lane >> 2;          // c-frag row group
    const int ccol = (lane & 3) * 2;     // c-frag col base

    if (is_src) {
        const int b = bx;
        float* dst = g_src_proj + (size_t)b * H_DIM * S_DIM;
#pragma unroll
        for (int mf = 0; mf < 2; mf++)
#pragma unroll
            for (int nf = 0; nf < 4; nf++) {
                const int s0 = wm + mf * 16 + crow;
                const int h0g = n0 + wn + nf * 8 + ccol;
                dst[(h0g    ) * S_DIM + s0    ] = acc[mf][nf][0] + bias[h0g    ];
                dst[(h0g + 1) * S_DIM + s0    ] = acc[mf][nf][1] + bias[h0g + 1];
                dst[(h0g    ) * S_DIM + s0 + 8] = acc[mf][nf][2] + bias[h0g    ];
                dst[(h0g + 1) * S_DIM + s0 + 8] = acc[mf][nf][3] + bias[h0g + 1];
            }
    } else {
        const int m0 = (bx - 32) * 128;
#pragma unroll
        for (int mf = 0; mf < 2; mf++)
#pragma unroll
            for (int nf = 0; nf < 4; nf++) {
                const int m = m0 + wm + mf * 16 + crow;
                const int h0g = n0 + wn + nf * 8 + ccol;
                g_q_proj[(size_t)m * H_DIM + h0g    ]       = acc[mf][nf][0] + bias[h0g    ];
                g_q_proj[(size_t)m * H_DIM + h0g + 1]       = acc[mf][nf][1] + bias[h0g + 1];
                g_q_proj[(size_t)(m + 8) * H_DIM + h0g    ] = acc[mf][nf][2] + bias[h0g    ];
                g_q_proj[(size_t)(m + 8) * H_DIM + h0g + 1] = acc[mf][nf][3] + bias[h0g + 1];
            }
    }
}

// ---------------------------------------------------------------------------
// Fused: tanh(src_proj + q_proj) . w2 + b2 -> mask -> softmax over s.
// (unchanged from R3: 512 thr, H split 4 ways, MUFU.TANH)
// ---------------------------------------------------------------------------
__global__ __launch_bounds__(512) void fused_attn(
    const float* __restrict__ w2, const float* __restrict__ b2p,
    const int* __restrict__ mask, float* __restrict__ out)
{
    const int b   = blockIdx.y;
    const int tg  = blockIdx.x;
    const int tid = threadIdx.x;
    const int s   = tid & 127;
    const int hg  = tid >> 7;

    __shared__ float qs[4][H_DIM];
    __shared__ float w2s[H_DIM];
    __shared__ float part[4][4][S_DIM];
    __shared__ float redm[4][4];
    __shared__ float reds[4][4];

    const float LOG2E = 1.442695040888963407f;

    for (int idx = tid; idx < 4 * H_DIM; idx += 512) {
        const int tt = idx >> 8;
        const int h  = idx & (H_DIM - 1);
        const int t  = tg * 4 + tt;
        qs[tt][h] = g_q_proj[((size_t)t * B_DIM + b) * H_DIM + h];
    }
    if (tid < H_DIM) w2s[tid] = w2[tid];
    __syncthreads();

    const float* __restrict__ srcb = g_src_proj + (size_t)b * H_DIM * S_DIM + s;
    const int h0 = hg * 64;

    float a0 = 0.f, a1 = 0.f, a2 = 0.f, a3 = 0.f;
#pragma unroll 8
    for (int i = 0; i < 64; i++) {
        const int h = h0 + i;
        const float sv = srcb[h * S_DIM];
        const float w  = w2s[h];
        a0 = fmaf(w, tanhf_(sv + qs[0][h]), a0);
        a1 = fmaf(w, tanhf_(sv + qs[1][h]), a1);
        a2 = fmaf(w, tanhf_(sv + qs[2][h]), a2);
        a3 = fmaf(w, tanhf_(sv + qs[3][h]), a3);
    }
    part[0][hg][s] = a0;
    part[1][hg][s] = a1;
    part[2][hg][s] = a2;
    part[3][hg][s] = a3;
    __syncthreads();

    float logit = ((part[hg][0][s] + part[hg][1][s]) +
                   (part[hg][2][s] + part[hg][3][s])) + b2p[0];
    if (mask[b * S_DIM + s] != 0)
        logit = __int_as_float(0xff800000);

    const int lane = tid & 31;
    const int gw   = (tid >> 5) & 3;

    float m = logit;
#pragma unroll
    for (int off = 16; off >= 1; off >>= 1)
        m = fmaxf(m, __shfl_xor_sync(0xffffffffu, m, off));
    if (lane == 0) redm[hg][gw] = m;
    __syncthreads();

    const float bm = fmaxf(fmaxf(redm[hg][0], redm[hg][1]),
                           fmaxf(redm[hg][2], redm[hg][3]));
    const float e = ex2f_((logit - bm) * LOG2E);
    float sum = e;
#pragma unroll
    for (int off = 16; off >= 1; off >>= 1)
        sum += __shfl_xor_sync(0xffffffffu, sum, off);
    if (lane == 0) reds[hg][gw] = sum;
    __syncthreads();

    const float tot = (reds[hg][0] + reds[hg][1]) + (reds[hg][2] + reds[hg][3]);
    const int t = tg * 4 + hg;
    out[((size_t)t * B_DIM + b) * S_DIM + s] = e / tot;
}

extern "C" void kernel_launch(void* const* d_in, const int* in_sizes, int n_in,
                              void* d_out, int out_size)
{
    const float* src  = (const float*)d_in[0];
    const int*   mask = (const int*)d_in[1];
    const float* qv   = (const float*)d_in[2];
    const float* Wsrc = (const float*)d_in[3];
    const float* bsrc = (const float*)d_in[4];
    const float* Wq   = (const float*)d_in[5];
    const float* bq   = (const float*)d_in[6];
    const float* w2   = (const float*)d_in[7];
    const float* b2   = (const float*)d_in[8];
    float*       out  = (float*)d_out;

    dim3 g1(48, 4);
    proj_gemm<<<g1, 256>>>(src, Wsrc, bsrc, qv, Wq, bq);

    dim3 g2(T_DIM / 4, B_DIM);
    fused_attn<<<g2, 512>>>(w2, b2, mask, out);
}

// round 5
// speedup vs baseline: 2.2986x; 1.5465x over previous
#include <cuda_runtime.h>
#include <math_constants.h>

#define T_DIM 64
#define B_DIM 32
#define S_DIM 128
#define E_DIM 512
#define Q_DIM 512
#define H_DIM 256

// Scratch (device globals — no allocation allowed)
__device__ float g_src_proj[B_DIM * H_DIM * S_DIM];   // [b][h][s]  (transposed for fused reads)
__device__ float g_q_proj[T_DIM * B_DIM * H_DIM];     // [t][b][h]

__device__ __forceinline__ float ex2f_(float x) {
    float y; asm("ex2.approx.f32 %0, %1;" : "=f"(y) : "f"(x)); return y;
}
__device__ __forceinline__ float tanhf_(float x) {
    float y; asm("tanh.approx.f32 %0, %1;" : "=f"(y) : "f"(x)); return y;
}
__device__ __forceinline__ unsigned tf32_(float x) {
    unsigned r; asm("cvt.rna.tf32.f32 %0, %1;" : "=r"(r) : "f"(x)); return r;
}
__device__ __forceinline__ void mma_tf32(float c[4], const unsigned a[4], const unsigned b[2]) {
    asm volatile(
        "mma.sync.aligned.m16n8k8.row.col.f32.tf32.tf32.f32 "
        "{%0,%1,%2,%3}, {%4,%5,%6,%7}, {%8,%9}, {%0,%1,%2,%3};"
        : "+f"(c[0]), "+f"(c[1]), "+f"(c[2]), "+f"(c[3])
        : "r"(a[0]), "r"(a[1]), "r"(a[2]), "r"(a[3]), "r"(b[0]), "r"(b[1]));
}

// ---------------------------------------------------------------------------
// Tensor-core projection GEMM — single-pass TF32 (rate-hypothesis experiment).
// C[m,h] = sum_k A[m,k] * W[h,k] + bias[h],  K=512.
// blockIdx.x in [0,32): src path, out transposed [b][h][s].
// blockIdx.x in [32,48): query path, out row-major [m][h].
// CTA tile 128(m) x 64(n), 8 warps in 4(m) x 2(n), warp tile 32x32.
// Smem K-chunk = 16, row stride 20 floats (conflict-free fragment LDS).
// ---------------------------------------------------------------------------
__global__ __launch_bounds__(256) void proj_gemm(
    const float* __restrict__ src, const float* __restrict__ Wsrc, const float* __restrict__ bsrc,
    const float* __restrict__ qv,  const float* __restrict__ Wq,   const float* __restrict__ bq)
{
    const int bx = blockIdx.x;      // 0..47
    const int n0 = blockIdx.y * 64; // h tile base

    const bool is_src = (bx < 32);
    const float* __restrict__ A    = is_src ? (src + (size_t)bx * 128 * E_DIM)
                                            : (qv  + (size_t)(bx - 32) * 128 * Q_DIM);
    const float* __restrict__ W    = is_src ? Wsrc : Wq;
    const float* __restrict__ bias = is_src ? bsrc : bq;

    __shared__ float Ahi[128][20];
    __shared__ float Bhi[64][20];

    const int tid  = threadIdx.x;
    const int warp = tid >> 5;
    const int lane = tid & 31;
    const int wm   = (warp & 3) * 32;   // warp m base
    const int wn   = (warp >> 2) * 32;  // warp n base
    const int frow = lane >> 2;         // fragment row group 0..7
    const int fcol = lane & 3;          // fragment col group 0..3

    float acc[2][4][4];
#pragma unroll
    for (int i = 0; i < 2; i++)
#pragma unroll
        for (int j = 0; j < 4; j++)
#pragma unroll
            for (int r = 0; r < 4; r++) acc[i][j][r] = 0.f;

    for (int kt = 0; kt < 512; kt += 16) {
        // --- load + tf32 (rna) convert into smem ---
        // A tile: 128 x 16 = 512 float4; 2 per thread
#pragma unroll
        for (int j = 0; j < 2; j++) {
            const int v = tid * 2 + j;
            const int r = v >> 2;
            const int c = (v & 3) * 4;
            float4 a = *(const float4*)&A[(size_t)r * 512 + kt + c];
            float av[4] = {a.x, a.y, a.z, a.w};
#pragma unroll
            for (int i = 0; i < 4; i++)
                Ahi[r][c + i] = __uint_as_float(tf32_(av[i]));
        }
        // W tile: 64 x 16 = 256 float4; 1 per thread
        {
            const int r = tid >> 2;
            const int c = (tid & 3) * 4;
            float4 w = *(const float4*)&W[(size_t)(n0 + r) * 512 + kt + c];
            float wv[4] = {w.x, w.y, w.z, w.w};
#pragma unroll
            for (int i = 0; i < 4; i++)
                Bhi[r][c + i] = __uint_as_float(tf32_(wv[i]));
        }
        __syncthreads();

        // --- 2 k-steps of mma ---
#pragma unroll
        for (int ks = 0; ks < 2; ks++) {
            const int k0 = ks * 8;

            unsigned ah[2][4];
#pragma unroll
            for (int mf = 0; mf < 2; mf++) {
                const int m = wm + mf * 16;
                ah[mf][0] = __float_as_uint(Ahi[m + frow    ][k0 + fcol    ]);
                ah[mf][1] = __float_as_uint(Ahi[m + frow + 8][k0 + fcol    ]);
                ah[mf][2] = __float_as_uint(Ahi[m + frow    ][k0 + fcol + 4]);
                ah[mf][3] = __float_as_uint(Ahi[m + frow + 8][k0 + fcol + 4]);
            }
            unsigned bh[4][2];
#pragma unroll
            for (int nf = 0; nf < 4; nf++) {
                const int n = wn + nf * 8;
                bh[nf][0] = __float_as_uint(Bhi[n + frow][k0 + fcol    ]);
                bh[nf][1] = __float_as_uint(Bhi[n + frow][k0 + fcol + 4]);
            }
#pragma unroll
            for (int mf = 0; mf < 2; mf++)
#pragma unroll
                for (int nf = 0; nf < 4; nf++)
                    mma_tf32(acc[mf][nf], ah[mf], bh[nf]);
        }
        __syncthreads();
    }

    // --- epilogue ---
    const int crow = lane >> 2;          // c-frag row group
    const int ccol = (lane & 3) * 2;     // c-frag col base

    if (is_src) {
        const int b = bx;
        float* dst = g_src_proj + (size_t)b * H_DIM * S_DIM;
#pragma unroll
        for (int mf = 0; mf < 2; mf++)
#pragma unroll
            for (int nf = 0; nf < 4; nf++) {
                const int s0 = wm + mf * 16 + crow;
                const int h0g = n0 + wn + nf * 8 + ccol;
                dst[(h0g    ) * S_DIM + s0    ] = acc[mf][nf][0] + bias[h0g    ];
                dst[(h0g + 1) * S_DIM + s0    ] = acc[mf][nf][1] + bias[h0g + 1];
                dst[(h0g    ) * S_DIM + s0 + 8] = acc[mf][nf][2] + bias[h0g    ];
                dst[(h0g + 1) * S_DIM + s0 + 8] = acc[mf][nf][3] + bias[h0g + 1];
            }
    } else {
        const int m0 = (bx - 32) * 128;
#pragma unroll
        for (int mf = 0; mf < 2; mf++)
#pragma unroll
            for (int nf = 0; nf < 4; nf++) {
                const int m = m0 + wm + mf * 16 + crow;
                const int h0g = n0 + wn + nf * 8 + ccol;
                g_q_proj[(size_t)m * H_DIM + h0g    ]       = acc[mf][nf][0] + bias[h0g    ];
                g_q_proj[(size_t)m * H_DIM + h0g + 1]       = acc[mf][nf][1] + bias[h0g + 1];
                g_q_proj[(size_t)(m + 8) * H_DIM + h0g    ] = acc[mf][nf][2] + bias[h0g    ];
                g_q_proj[(size_t)(m + 8) * H_DIM + h0g + 1] = acc[mf][nf][3] + bias[h0g + 1];
            }
    }
}

// ---------------------------------------------------------------------------
// Fused: tanh(src_proj + q_proj) . w2 + b2 -> mask -> softmax over s.
// (unchanged: 512 thr, H split 4 ways, MUFU.TANH)
// ---------------------------------------------------------------------------
__global__ __launch_bounds__(512) void fused_attn(
    const float* __restrict__ w2, const float* __restrict__ b2p,
    const int* __restrict__ mask, float* __restrict__ out)
{
    const int b   = blockIdx.y;
    const int tg  = blockIdx.x;
    const int tid = threadIdx.x;
    const int s   = tid & 127;
    const int hg  = tid >> 7;

    __shared__ float qs[4][H_DIM];
    __shared__ float w2s[H_DIM];
    __shared__ float part[4][4][S_DIM];
    __shared__ float redm[4][4];
    __shared__ float reds[4][4];

    const float LOG2E = 1.442695040888963407f;

    for (int idx = tid; idx < 4 * H_DIM; idx += 512) {
        const int tt = idx >> 8;
        const int h  = idx & (H_DIM - 1);
        const int t  = tg * 4 + tt;
        qs[tt][h] = g_q_proj[((size_t)t * B_DIM + b) * H_DIM + h];
    }
    if (tid < H_DIM) w2s[tid] = w2[tid];
    __syncthreads();

    const float* __restrict__ srcb = g_src_proj + (size_t)b * H_DIM * S_DIM + s;
    const int h0 = hg * 64;

    float a0 = 0.f, a1 = 0.f, a2 = 0.f, a3 = 0.f;
#pragma unroll 8
    for (int i = 0; i < 64; i++) {
        const int h = h0 + i;
        const float sv = srcb[h * S_DIM];
        const float w  = w2s[h];
        a0 = fmaf(w, tanhf_(sv + qs[0][h]), a0);
        a1 = fmaf(w, tanhf_(sv + qs[1][h]), a1);
        a2 = fmaf(w, tanhf_(sv + qs[2][h]), a2);
        a3 = fmaf(w, tanhf_(sv + qs[3][h]), a3);
    }
    part[0][hg][s] = a0;
    part[1][hg][s] = a1;
    part[2][hg][s] = a2;
    part[3][hg][s] = a3;
    __syncthreads();

    float logit = ((part[hg][0][s] + part[hg][1][s]) +
                   (part[hg][2][s] + part[hg][3][s])) + b2p[0];
    if (mask[b * S_DIM + s] != 0)
        logit = __int_as_float(0xff800000);

    const int lane = tid & 31;
    const int gw   = (tid >> 5) & 3;

    float m = logit;
#pragma unroll
    for (int off = 16; off >= 1; off >>= 1)
        m = fmaxf(m, __shfl_xor_sync(0xffffffffu, m, off));
    if (lane == 0) redm[hg][gw] = m;
    __syncthreads();

    const float bm = fmaxf(fmaxf(redm[hg][0], redm[hg][1]),
                           fmaxf(redm[hg][2], redm[hg][3]));
    const float e = ex2f_((logit - bm) * LOG2E);
    float sum = e;
#pragma unroll
    for (int off = 16; off >= 1; off >>= 1)
        sum += __shfl_xor_sync(0xffffffffu, sum, off);
    if (lane == 0) reds[hg][gw] = sum;
    __syncthreads();

    const float tot = (reds[hg][0] + reds[hg][1]) + (reds[hg][2] + reds[hg][3]);
    const int t = tg * 4 + hg;
    out[((size_t)t * B_DIM + b) * S_DIM + s] = e / tot;
}

extern "C" void kernel_launch(void* const* d_in, const int* in_sizes, int n_in,
                              void* d_out, int out_size)
{
    const float* src  = (const float*)d_in[0];
    const int*   mask = (const int*)d_in[1];
    const float* qv   = (const float*)d_in[2];
    const float* Wsrc = (const float*)d_in[3];
    const float* bsrc = (const float*)d_in[4];
    const float* Wq   = (const float*)d_in[5];
    const float* bq   = (const float*)d_in[6];
    const float* w2   = (const float*)d_in[7];
    const float* b2   = (const float*)d_in[8];
    float*       out  = (float*)d_out;

    dim3 g1(48, 4);
    proj_gemm<<<g1, 256>>>(src, Wsrc, bsrc, qv, Wq, bq);

    dim3 g2(T_DIM / 4, B_DIM);
    fused_attn<<<g2, 512>>>(w2, b2, mask, out);
}

// round 7
// speedup vs baseline: 2.6877x; 1.1693x over previous
#include <cuda_runtime.h>
#include <cstdint>
#include <math_constants.h>

#define T_DIM 64
#define B_DIM 32
#define S_DIM 128
#define E_DIM 512
#define Q_DIM 512
#define H_DIM 256

#define GEMM_BK   32
#define GEMM_PAD  36   // floats per smem row (32 data + 4 pad): conflict-free frags

// Scratch (device globals — no allocation allowed)
__device__ float g_src_proj[B_DIM * H_DIM * S_DIM];   // [b][h][s]
__device__ float g_q_proj[T_DIM * B_DIM * H_DIM];     // [t][b][h]

__device__ __forceinline__ float ex2f_(float x) {
    float y; asm("ex2.approx.f32 %0, %1;" : "=f"(y) : "f"(x)); return y;
}
__device__ __forceinline__ float tanhf_(float x) {
    float y; asm("tanh.approx.f32 %0, %1;" : "=f"(y) : "f"(x)); return y;
}
__device__ __forceinline__ void mma_tf32(float c[4], const unsigned a[4], const unsigned b[2]) {
    asm volatile(
        "mma.sync.aligned.m16n8k8.row.col.f32.tf32.tf32.f32 "
        "{%0,%1,%2,%3}, {%4,%5,%6,%7}, {%8,%9}, {%0,%1,%2,%3};"
        : "+f"(c[0]), "+f"(c[1]), "+f"(c[2]), "+f"(c[3])
        : "r"(a[0]), "r"(a[1]), "r"(a[2]), "r"(a[3]), "r"(b[0]), "r"(b[1]));
}
__device__ __forceinline__ void cp_async16(uint32_t saddr, const void* gptr) {
    asm volatile("cp.async.cg.shared.global [%0], [%1], 16;" :: "r"(saddr), "l"(gptr));
}

// ---------------------------------------------------------------------------
// Tensor-core projection GEMM — TF32 (HW truncation), cp.async double-buffered.
// C[m,h] = sum_k A[m,k] * W[h,k] + bias[h],  K=512.
// blockIdx.x in [0,32): src path, out transposed [b][h][s].
// blockIdx.x in [32,48): query path, out row-major [m][h].
// CTA tile 128(m) x 64(n), 512 threads = 16 warps in 4(m) x 4(n), warp 32x16.
// ---------------------------------------------------------------------------
__global__ __launch_bounds__(512) void proj_gemm(
    const float* __restrict__ src, const float* __restrict__ Wsrc, const float* __restrict__ bsrc,
    const float* __restrict__ qv,  const float* __restrict__ Wq,   const float* __restrict__ bq)
{
    extern __shared__ float sm[];
    float* As = sm;                        // [2][128][GEMM_PAD]
    float* Bs = sm + 2 * 128 * GEMM_PAD;   // [2][64][GEMM_PAD]

    const int bx = blockIdx.x;      // 0..47
    const int n0 = blockIdx.y * 64; // h tile base

    const bool is_src = (bx < 32);
    const float* __restrict__ A    = is_src ? (src + (size_t)bx * 128 * E_DIM)
                                            : (qv  + (size_t)(bx - 32) * 128 * Q_DIM);
    const float* __restrict__ W    = is_src ? Wsrc : Wq;
    const float* __restrict__ bias = is_src ? bsrc : bq;

    const int tid  = threadIdx.x;
    const int warp = tid >> 5;          // 0..15
    const int lane = tid & 31;
    const int wm   = (warp & 3) * 32;   // warp m base
    const int wn   = (warp >> 2) * 16;  // warp n base
    const int frow = lane >> 2;         // 0..7
    const int fcol = lane & 3;          // 0..3

    const uint32_t As_base = (uint32_t)__cvta_generic_to_shared(As);
    const uint32_t Bs_base = (uint32_t)__cvta_generic_to_shared(Bs);

    float acc[2][2][4];
#pragma unroll
    for (int i = 0; i < 2; i++)
#pragma unroll
        for (int j = 0; j < 2; j++)
#pragma unroll
            for (int r = 0; r < 4; r++) acc[i][j][r] = 0.f;

    auto load_chunk = [&](int kc, int buf) {
        const int kt = kc * GEMM_BK;
        const uint32_t abuf = As_base + (uint32_t)buf * 128 * GEMM_PAD * 4;
        const uint32_t bbuf = Bs_base + (uint32_t)buf * 64 * GEMM_PAD * 4;
#pragma unroll
        for (int j = 0; j < 2; j++) {
            const int v = tid + j * 512;      // 0..1023
            const int r = v >> 3;             // 0..127
            const int c = (v & 7) * 4;        // 0..28
            cp_async16(abuf + (uint32_t)(r * GEMM_PAD + c) * 4,
                       &A[(size_t)r * 512 + kt + c]);
        }
        {
            const int r = tid >> 3;           // 0..63
            const int c = (tid & 7) * 4;
            cp_async16(bbuf + (uint32_t)(r * GEMM_PAD + c) * 4,
                       &W[(size_t)(n0 + r) * 512 + kt + c]);
        }
        asm volatile("cp.async.commit_group;");
    };

    load_chunk(0, 0);

    for (int kc = 0; kc < 16; kc++) {
        if (kc + 1 < 16) {
            load_chunk(kc + 1, (kc + 1) & 1);
            asm volatile("cp.async.wait_group 1;");
        } else {
            asm volatile("cp.async.wait_group 0;");
        }
        __syncthreads();

        const int buf = kc & 1;
        const float* Ab = As + buf * 128 * GEMM_PAD;
        const float* Bb = Bs + buf * 64 * GEMM_PAD;

#pragma unroll
        for (int ks = 0; ks < 4; ks++) {
            const int k0 = ks * 8;
            unsigned ah[2][4];
#pragma unroll
            for (int mf = 0; mf < 2; mf++) {
                const int m = wm + mf * 16;
                ah[mf][0] = __float_as_uint(Ab[(m + frow    ) * GEMM_PAD + k0 + fcol    ]);
                ah[mf][1] = __float_as_uint(Ab[(m + frow + 8) * GEMM_PAD + k0 + fcol    ]);
                ah[mf][2] = __float_as_uint(Ab[(m + frow    ) * GEMM_PAD + k0 + fcol + 4]);
                ah[mf][3] = __float_as_uint(Ab[(m + frow + 8) * GEMM_PAD + k0 + fcol + 4]);
            }
            unsigned bh[2][2];
#pragma unroll
            for (int nf = 0; nf < 2; nf++) {
                const int n = wn + nf * 8;
                bh[nf][0] = __float_as_uint(Bb[(n + frow) * GEMM_PAD + k0 + fcol    ]);
                bh[nf][1] = __float_as_uint(Bb[(n + frow) * GEMM_PAD + k0 + fcol + 4]);
            }
#pragma unroll
            for (int mf = 0; mf < 2; mf++)
#pragma unroll
                for (int nf = 0; nf < 2; nf++)
                    mma_tf32(acc[mf][nf], ah[mf], bh[nf]);
        }
        __syncthreads();
    }

    // --- epilogue ---
    const int crow = lane >> 2;
    const int ccol = (lane & 3) * 2;

    if (is_src) {
        const int b = bx;
        float* dst = g_src_proj + (size_t)b * H_DIM * S_DIM;
#pragma unroll
        for (int mf = 0; mf < 2; mf++)
#pragma unroll
            for (int nf = 0; nf < 2; nf++) {
                const int s0  = wm + mf * 16 + crow;
                const int h0g = n0 + wn + nf * 8 + ccol;
                dst[(h0g    ) * S_DIM + s0    ] = acc[mf][nf][0] + bias[h0g    ];
                dst[(h0g + 1) * S_DIM + s0    ] = acc[mf][nf][1] + bias[h0g + 1];
                dst[(h0g    ) * S_DIM + s0 + 8] = acc[mf][nf][2] + bias[h0g    ];
                dst[(h0g + 1) * S_DIM + s0 + 8] = acc[mf][nf][3] + bias[h0g + 1];
            }
    } else {
        const int m0 = (bx - 32) * 128;
#pragma unroll
        for (int mf = 0; mf < 2; mf++)
#pragma unroll
            for (int nf = 0; nf < 2; nf++) {
                const int m   = m0 + wm + mf * 16 + crow;
                const int h0g = n0 + wn + nf * 8 + ccol;
                g_q_proj[(size_t)m * H_DIM + h0g    ]       = acc[mf][nf][0] + bias[h0g    ];
                g_q_proj[(size_t)m * H_DIM + h0g + 1]       = acc[mf][nf][1] + bias[h0g + 1];
                g_q_proj[(size_t)(m + 8) * H_DIM + h0g    ] = acc[mf][nf][2] + bias[h0g    ];
                g_q_proj[(size_t)(m + 8) * H_DIM + h0g + 1] = acc[mf][nf][3] + bias[h0g + 1];
            }
    }
}

// ---------------------------------------------------------------------------
// Fused: tanh(src_proj + q_proj) . w2 + b2 -> mask -> softmax over s.
// (unchanged: 512 thr, H split 4 ways, MUFU.TANH)
// ---------------------------------------------------------------------------
__global__ __launch_bounds__(512) void fused_attn(
    const float* __restrict__ w2, const float* __restrict__ b2p,
    const int* __restrict__ mask, float* __restrict__ out)
{
    const int b   = blockIdx.y;
    const int tg  = blockIdx.x;
    const int tid = threadIdx.x;
    const int s   = tid & 127;
    const int hg  = tid >> 7;

    __shared__ float qs[4][H_DIM];
    __shared__ float w2s[H_DIM];
    __shared__ float part[4][4][S_DIM];
    __shared__ float redm[4][4];
    __shared__ float reds[4][4];

    const float LOG2E = 1.442695040888963407f;

    for (int idx = tid; idx < 4 * H_DIM; idx += 512) {
        const int tt = idx >> 8;
        const int h  = idx & (H_DIM - 1);
        const int t  = tg * 4 + tt;
        qs[tt][h] = g_q_proj[((size_t)t * B_DIM + b) * H_DIM + h];
    }
    if (tid < H_DIM) w2s[tid] = w2[tid];
    __syncthreads();

    const float* __restrict__ srcb = g_src_proj + (size_t)b * H_DIM * S_DIM + s;
    const int h0 = hg * 64;

    float a0 = 0.f, a1 = 0.f, a2 = 0.f, a3 = 0.f;
#pragma unroll 8
    for (int i = 0; i < 64; i++) {
        const int h = h0 + i;
        const float sv = srcb[h * S_DIM];
        const float w  = w2s[h];
        a0 = fmaf(w, tanhf_(sv + qs[0][h]), a0);
        a1 = fmaf(w, tanhf_(sv + qs[1][h]), a1);
        a2 = fmaf(w, tanhf_(sv + qs[2][h]), a2);
        a3 = fmaf(w, tanhf_(sv + qs[3][h]), a3);
    }
    part[0][hg][s] = a0;
    part[1][hg][s] = a1;
    part[2][hg][s] = a2;
    part[3][hg][s] = a3;
    __syncthreads();

    float logit = ((part[hg][0][s] + part[hg][1][s]) +
                   (part[hg][2][s] + part[hg][3][s])) + b2p[0];
    if (mask[b * S_DIM + s] != 0)
        logit = __int_as_float(0xff800000);

    const int lane = tid & 31;
    const int gw   = (tid >> 5) & 3;

    float m = logit;
#pragma unroll
    for (int off = 16; off >= 1; off >>= 1)
        m = fmaxf(m, __shfl_xor_sync(0xffffffffu, m, off));
    if (lane == 0) redm[hg][gw] = m;
    __syncthreads();

    const float bm = fmaxf(fmaxf(redm[hg][0], redm[hg][1]),
                           fmaxf(redm[hg][2], redm[hg][3]));
    const float e = ex2f_((logit - bm) * LOG2E);
    float sum = e;
#pragma unroll
    for (int off = 16; off >= 1; off >>= 1)
        sum += __shfl_xor_sync(0xffffffffu, sum, off);
    if (lane == 0) reds[hg][gw] = sum;
    __syncthreads();

    const float tot = (reds[hg][0] + reds[hg][1]) + (reds[hg][2] + reds[hg][3]);
    const int t = tg * 4 + hg;
    out[((size_t)t * B_DIM + b) * S_DIM + s] = e / tot;
}

extern "C" void kernel_launch(void* const* d_in, const int* in_sizes, int n_in,
                              void* d_out, int out_size)
{
    const float* src  = (const float*)d_in[0];
    const int*   mask = (const int*)d_in[1];
    const float* qv   = (const float*)d_in[2];
    const float* Wsrc = (const float*)d_in[3];
    const float* bsrc = (const float*)d_in[4];
    const float* Wq   = (const float*)d_in[5];
    const float* bq   = (const float*)d_in[6];
    const float* w2   = (const float*)d_in[7];
    const float* b2   = (const float*)d_in[8];
    float*       out  = (float*)d_out;

    const int smem_bytes = (2 * 128 * GEMM_PAD + 2 * 64 * GEMM_PAD) * 4;  // 55296
    cudaFuncSetAttribute(proj_gemm, cudaFuncAttributeMaxDynamicSharedMemorySize, smem_bytes);

    dim3 g1(48, 4);
    proj_gemm<<<g1, 512, smem_bytes>>>(src, Wsrc, bsrc, qv, Wq, bq);

    dim3 g2(T_DIM / 4, B_DIM);
    fused_attn<<<g2, 512>>>(w2, b2, mask, out);
}